// round 16
// baseline (speedup 1.0000x reference)
#include <cuda_runtime.h>
#include <cuda_fp16.h>
#include <math.h>
#include <stdint.h>

#define NPTS      524288
#define GRIDSZ    512
#define NC        36
#define KIN       129
#define HID       256
#define NOUT      129
#define TB        64
#define NTHREADS  256

// ---- smem byte layout (per CTA, 4 CTAs/SM, 52800 B) ----
// phase1: W1 chunk dbl buf [0,24576) ; W1 tail [24576,28672) ; A1 [33792,51200)
// phase2: A2 [0,33792) ; W2 chunk dbl buf [33792,47616)
// biases: b1s(100*b1) [51200,52224) ; b2s [52224,52800)
#define BY_WC   0
#define CH1_SZ  12288      // 256 rows x 48 B
#define BY_WT   24576      // 256 rows x 16 B
#define BY_A2   0
#define BY_W2C  33792
#define CH2_SZ  6912       // 144 rows x 48 B
#define BY_A1   33792
#define BY_B1S  51200
#define BY_B2S  52224
#define SMEM_BYTES 52800

#define SWC_B 48          // chunk row stride; 3r mod 8 bijection -> ldsm conflict-free
#define SA1_B 272         // A1 row stride; r mod 8 distinct
#define SA2_B 528         // A2 row stride
#define N2PAD 144

__device__ __align__(16) __half g_planesTh[3*GRIDSZ*GRIDSZ*NC]; // [i][y][x][c]
__device__ __align__(16) __half g_linesTh[3*GRIDSZ*NC];
__device__ __align__(16) __half g_W1c[8*256*16];  // [chunk][n][k'] k=0..127
__device__ __align__(16) __half g_W1t[256*8];     // [n][k'] k=128..135 (zero-padded)
__device__ __align__(16) __half g_W2c[16*144*16]; // [chunk][n][k'] n zero-padded >=129

// ================= prep kernels =================
__global__ void __launch_bounds__(256) transpose_planes(const float* __restrict__ planes) {
    __shared__ float tile[8][32*37];
    int wid = threadIdx.x >> 5, lane = threadIdx.x & 31;
    int cell0 = (blockIdx.x * 8 + wid) * 32;
    int i = cell0 / (GRIDSZ*GRIDSZ);
    int rem = cell0 - i*GRIDSZ*GRIDSZ;
    int y = rem >> 9, x0 = rem & (GRIDSZ-1);
    const float* src = planes + (long)i*NC*GRIDSZ*GRIDSZ + (long)y*GRIDSZ + x0 + lane;
    float* t = tile[wid];
    #pragma unroll
    for (int c = 0; c < NC; c++) t[lane*37 + c] = src[(long)c*GRIDSZ*GRIDSZ];
    __syncwarp();
    __half2* dst = (__half2*)(g_planesTh + (long)cell0 * NC);
    #pragma unroll
    for (int k = 0; k < 18; k++) {
        int h2i = k*32 + lane;
        int e0 = h2i*2;
        int cc = e0 / NC, c = e0 - cc*NC;
        dst[h2i] = __floats2half2_rn(t[cc*37+c], t[cc*37+c+1]);
    }
}

__global__ void transpose_lines(const float* __restrict__ lines) {
    int t2 = blockIdx.x * blockDim.x + threadIdx.x;
    if (t2 < 3*GRIDSZ) {
        int j = t2 & (GRIDSZ-1), i = t2 >> 9;
        __half* dst = g_linesTh + t2*NC;
        const float* src = lines + (long)i*NC*GRIDSZ + j;
        #pragma unroll
        for (int c = 0; c < NC; c++) dst[c] = __float2half_rn(src[(long)c*GRIDSZ]);
    }
}

__global__ void pack_weights_kernel(const float* __restrict__ W1, const float* __restrict__ W2) {
    int idx = blockIdx.x * blockDim.x + threadIdx.x;
    const int T1 = 8*256*16;            // 32768
    const int T2 = 256*8;               // 2048
    const int T3 = 16*144*16;           // 36864
    if (idx < T1) {
        int c = idx >> 12, rem = idx & 4095;
        int n = rem >> 4, kp = rem & 15;
        int k = c*16 + kp;              // 0..127 < KIN
        g_W1c[idx] = __float2half_rn(W1[k*HID + n]);
    } else if (idx < T1 + T2) {
        int j = idx - T1;
        int n = j >> 3, kp = j & 7;
        int k = 128 + kp;
        g_W1t[j] = (k < KIN) ? __float2half_rn(W1[k*HID + n]) : __float2half_rn(0.f);
    } else if (idx < T1 + T2 + T3) {
        int j = idx - T1 - T2;
        int c = j / 2304, r = j - c*2304;
        int n = r >> 4, kp = r & 15;
        int k = c*16 + kp;
        float v = (n < NOUT) ? W2[k*NOUT + n] : 0.f;
        g_W2c[j] = __float2half_rn(v);
    }
}

// ================= mma / ldmatrix helpers =================
__device__ __forceinline__ void mma_f16_k16(float c[4], unsigned a0, unsigned a1,
                                            unsigned a2, unsigned a3,
                                            unsigned b0, unsigned b1) {
    asm volatile(
        "mma.sync.aligned.m16n8k16.row.col.f32.f16.f16.f32 "
        "{%0,%1,%2,%3},{%4,%5,%6,%7},{%8,%9},{%0,%1,%2,%3};"
        : "+f"(c[0]), "+f"(c[1]), "+f"(c[2]), "+f"(c[3])
        : "r"(a0), "r"(a1), "r"(a2), "r"(a3), "r"(b0), "r"(b1));
}
__device__ __forceinline__ void mma_h_k16(unsigned& d0, unsigned& d1,
                                          unsigned a0, unsigned a1, unsigned a2, unsigned a3,
                                          unsigned b0, unsigned b1) {
    asm volatile(
        "mma.sync.aligned.m16n8k16.row.col.f16.f16.f16.f16 "
        "{%0,%1},{%2,%3,%4,%5},{%6,%7},{%0,%1};"
        : "+r"(d0), "+r"(d1)
        : "r"(a0), "r"(a1), "r"(a2), "r"(a3), "r"(b0), "r"(b1));
}
__device__ __forceinline__ void mma_h_k8(unsigned& d0, unsigned& d1,
                                         unsigned a0, unsigned a1, unsigned b0) {
    asm volatile(
        "mma.sync.aligned.m16n8k8.row.col.f16.f16.f16.f16 "
        "{%0,%1},{%2,%3},{%4},{%0,%1};"
        : "+r"(d0), "+r"(d1) : "r"(a0), "r"(a1), "r"(b0));
}
__device__ __forceinline__ void ldsm_x4(unsigned& r0, unsigned& r1, unsigned& r2, unsigned& r3,
                                        uint32_t a) {
    asm volatile("ldmatrix.sync.aligned.m8n8.x4.shared.b16 {%0,%1,%2,%3}, [%4];"
                 : "=r"(r0), "=r"(r1), "=r"(r2), "=r"(r3) : "r"(a));
}
__device__ __forceinline__ void ldsm_x2(unsigned& r0, unsigned& r1, uint32_t a) {
    asm volatile("ldmatrix.sync.aligned.m8n8.x2.shared.b16 {%0,%1}, [%2];"
                 : "=r"(r0), "=r"(r1) : "r"(a));
}

__device__ __forceinline__ float softplus100b(float z, float b100) {
    float y = fmaf(z, 100.f, b100);
    float e = __expf(-fabsf(y));
    return 0.01f * (fmaxf(y, 0.f) + __logf(1.f + e));
}
__device__ __forceinline__ void cp16(uint32_t dst, const void* src) {
    asm volatile("cp.async.cg.shared.global [%0], [%1], 16;" :: "r"(dst), "l"(src));
}
__device__ __forceinline__ void cp_commit() { asm volatile("cp.async.commit_group;"); }
__device__ __forceinline__ void cp_wait0()  { asm volatile("cp.async.wait_group 0;" ::: "memory"); }

// ================= main fused kernel (4 CTAs/SM) =================
__global__ void __launch_bounds__(NTHREADS, 4)
tensosdf_main(const float* __restrict__ xyz,
              const float* __restrict__ b1, const float* __restrict__ b2,
              float* __restrict__ out) {
    extern __shared__ char smem[];
    const uint32_t smem_u32 = (uint32_t)__cvta_generic_to_shared(smem);
    float* b1s = (float*)(smem + BY_B1S);   // 100*b1
    float* b2s = (float*)(smem + BY_B2S);

    const int tid  = threadIdx.x;
    const int lane = tid & 31;
    const int warp = tid >> 5;            // 0..7
    const int pbase = blockIdx.x * TB;
    const int g = lane >> 2;
    const int t = lane & 3;

    // ---- biases ----
    b1s[tid] = 100.f * b1[tid];
    if (tid < N2PAD) b2s[tid] = (tid < NOUT) ? b2[tid] : 0.f;

    // ---- prestage W1 chunk 0 + tail (overlaps gather) ----
    {
        int n = tid >> 1, p = tid & 1;
        cp16(smem_u32 + BY_WC + (uint32_t)(n*SWC_B + p*16), (const char*)g_W1c + n*32 + p*16);
        int idx2 = tid + 256;
        int n2 = idx2 >> 1, p2 = idx2 & 1;
        cp16(smem_u32 + BY_WC + (uint32_t)(n2*SWC_B + p2*16), (const char*)g_W1c + n2*32 + p2*16);
        cp16(smem_u32 + BY_WT + (uint32_t)tid*16u, (const char*)g_W1t + tid*16);
    }
    cp_commit();

    // ---- gather: warp handles 8 points, fp16 tables, writes fp16 A1 ----
    {
        const unsigned FULL = 0xffffffffu;
        float vload = 0.f;
        int base3 = (pbase + warp*8)*3;
        if (lane < 24) vload = xyz[base3 + lane];

        const int i_of = (lane < 9) ? 0 : ((lane < 18) ? 1 : 2);
        const int cj = (lane - i_of*9) * 4;
        const bool act = lane < 27;
        const int fcol = i_of*NC + cj;
        const int pcol = 108 + lane;

        #pragma unroll
        for (int pi = 0; pi < 8; pi++) {
            float x0 = __shfl_sync(FULL, vload, pi*3+0);
            float x1 = __shfl_sync(FULL, vload, pi*3+1);
            float x2 = __shfl_sync(FULL, vload, pi*3+2);
            float xn0 = 2.f*x0 - 1.f, xn1 = 2.f*x1 - 1.f, xn2 = 2.f*x2 - 1.f;
            int row = warp*8 + pi;
            char* rbase = smem + BY_A1 + row*SA1_B;

            if (act) {
                float gx = (i_of == 2) ? xn1 : xn0;
                float gy = (i_of == 0) ? xn1 : xn2;
                float gl = (i_of == 0) ? xn2 : ((i_of == 1) ? xn1 : xn0);
                float px = (gx + 1.f) * 0.5f * 511.f;
                float py = (gy + 1.f) * 0.5f * 511.f;
                float pl = (gl + 1.f) * 0.5f * 511.f;
                int ix = min(max((int)floorf(px), 0), 510);
                int iy = min(max((int)floorf(py), 0), 510);
                int il = min(max((int)floorf(pl), 0), 510);
                float wx = px - ix, wy = py - iy, wl = pl - il;
                const __half* pb = g_planesTh + ((long)((i_of*GRIDSZ + iy)*GRIDSZ) + ix)*NC + cj;
                const __half* lb = g_linesTh + (i_of*GRIDSZ + il)*NC + cj;
                uint2 u00 = *(const uint2*)pb;
                uint2 u01 = *(const uint2*)(pb + NC);
                uint2 u10 = *(const uint2*)(pb + GRIDSZ*NC);
                uint2 u11 = *(const uint2*)(pb + GRIDSZ*NC + NC);
                uint2 ul0 = *(const uint2*)lb;
                uint2 ul1 = *(const uint2*)(lb + NC);
                float2 f00a = __half22float2(*(__half2*)&u00.x), f00b = __half22float2(*(__half2*)&u00.y);
                float2 f01a = __half22float2(*(__half2*)&u01.x), f01b = __half22float2(*(__half2*)&u01.y);
                float2 f10a = __half22float2(*(__half2*)&u10.x), f10b = __half22float2(*(__half2*)&u10.y);
                float2 f11a = __half22float2(*(__half2*)&u11.x), f11b = __half22float2(*(__half2*)&u11.y);
                float2 l0a  = __half22float2(*(__half2*)&ul0.x), l0b  = __half22float2(*(__half2*)&ul0.y);
                float2 l1a  = __half22float2(*(__half2*)&ul1.x), l1b  = __half22float2(*(__half2*)&ul1.y);
                float rx, ry, rz, rw;
                float fx0, fx1;
                fx0 = f00a.x + wx*(f01a.x - f00a.x); fx1 = f10a.x + wx*(f11a.x - f10a.x);
                rx = (fx0 + wy*(fx1 - fx0)) * (l0a.x + wl*(l1a.x - l0a.x));
                fx0 = f00a.y + wx*(f01a.y - f00a.y); fx1 = f10a.y + wx*(f11a.y - f10a.y);
                ry = (fx0 + wy*(fx1 - fx0)) * (l0a.y + wl*(l1a.y - l0a.y));
                fx0 = f00b.x + wx*(f01b.x - f00b.x); fx1 = f10b.x + wx*(f11b.x - f10b.x);
                rz = (fx0 + wy*(fx1 - fx0)) * (l0b.x + wl*(l1b.x - l0b.x));
                fx0 = f00b.y + wx*(f01b.y - f00b.y); fx1 = f10b.y + wx*(f11b.y - f10b.y);
                rw = (fx0 + wy*(fx1 - fx0)) * (l0b.y + wl*(l1b.y - l0b.y));
                *(__half2*)(rbase + fcol*2)     = __floats2half2_rn(rx, ry);
                *(__half2*)(rbase + fcol*2 + 4) = __floats2half2_rn(rz, rw);
            }

            float pv;
            if (lane < 3) pv = (lane == 0) ? xn0 : ((lane == 1) ? xn1 : xn2);
            else if (lane < 21) {
                int j = lane - 3, f = j / 6, rr = j - 6*f, d = rr % 3;
                float xv = ((d == 0) ? xn0 : ((d == 1) ? xn1 : xn2)) * (float)(1 << f);
                pv = (rr < 3) ? __sinf(xv) : __cosf(xv);
            } else pv = 0.f;
            if (pcol < 136)
                *(__half*)(rbase + pcol*2) = __float2half_rn(pv);
        }
    }

    cp_wait0();
    __syncthreads();

    // ================= GEMM1: 8 warps = 2m(32) x 4n(64), 8 k16-chunks, fp16 acc ======
    const int mt = warp & 1;
    const int nq = warp >> 1;          // 0..3
    const int arow = mt * 32;

    const int lrow  = (lane & 7) + ((lane >> 3) & 1) * 8;
    const int koffb = (lane >> 4) * 16;

    const uint32_t aAddr1 = smem_u32 + BY_A1 + (uint32_t)(arow + lrow)*SA1_B + koffb;
    const uint32_t bRow1  = (uint32_t)(nq*64 + lrow)*SWC_B + koffb;

    unsigned acch[2][8][2];
    #pragma unroll
    for (int i = 0; i < 2; i++)
        #pragma unroll
        for (int j = 0; j < 8; j++) { acch[i][j][0] = 0u; acch[i][j][1] = 0u; }

    // --- k8 tail first (k=128..135) from WT buffer ---
    {
        unsigned a0, a1, a4, a5;
        ldsm_x2(a0, a1, smem_u32 + BY_A1 + (uint32_t)(arow + lrow)*SA1_B + 256);
        ldsm_x2(a4, a5, smem_u32 + BY_A1 + (uint32_t)(arow + 16 + lrow)*SA1_B + 256);
        #pragma unroll
        for (int p = 0; p < 4; p++) {
            unsigned b0, b1x;
            ldsm_x2(b0, b1x, smem_u32 + BY_WT + (uint32_t)(nq*64 + p*16 + lrow)*16);
            mma_h_k8(acch[0][2*p][0],   acch[0][2*p][1],   a0, a1, b0);
            mma_h_k8(acch[0][2*p+1][0], acch[0][2*p+1][1], a0, a1, b1x);
            mma_h_k8(acch[1][2*p][0],   acch[1][2*p][1],   a4, a5, b0);
            mma_h_k8(acch[1][2*p+1][0], acch[1][2*p+1][1], a4, a5, b1x);
        }
    }

    // --- 8 chunks of 16 k ---
    #pragma unroll 1
    for (int c = 0; c < 8; c++) {
        if (c < 7) {
            uint32_t dbase = smem_u32 + BY_WC + (uint32_t)(((c+1)&1)*CH1_SZ);
            const char* src = (const char*)g_W1c + (c+1)*8192;
            int n = tid >> 1, p = tid & 1;
            cp16(dbase + (uint32_t)(n*SWC_B + p*16), src + n*32 + p*16);
            int idx2 = tid + 256;
            int n2 = idx2 >> 1, p2 = idx2 & 1;
            cp16(dbase + (uint32_t)(n2*SWC_B + p2*16), src + n2*32 + p2*16);
            cp_commit();
        }
        uint32_t bufb = smem_u32 + BY_WC + (uint32_t)((c&1)*CH1_SZ);
        unsigned a0, a1, a2, a3, a4, a5, a6, a7;
        ldsm_x4(a0, a1, a2, a3, aAddr1 + c*32);
        ldsm_x4(a4, a5, a6, a7, aAddr1 + 16*SA1_B + c*32);
        #pragma unroll
        for (int p = 0; p < 4; p++) {
            unsigned b0, b1x, b2x, b3;
            ldsm_x4(b0, b1x, b2x, b3, bufb + bRow1 + (uint32_t)p*16*SWC_B);
            mma_h_k16(acch[0][2*p][0],   acch[0][2*p][1],   a0, a1, a2, a3, b0, b2x);
            mma_h_k16(acch[0][2*p+1][0], acch[0][2*p+1][1], a0, a1, a2, a3, b1x, b3);
            mma_h_k16(acch[1][2*p][0],   acch[1][2*p][1],   a4, a5, a6, a7, b0, b2x);
            mma_h_k16(acch[1][2*p+1][0], acch[1][2*p+1][1], a4, a5, a6, a7, b1x, b3);
        }
        if (c < 7) cp_wait0();
        __syncthreads();
    }

    // ---- stage W2 chunk 0 (A1 now dead; region aliases A1) ----
    {
        int n = tid >> 1, p = tid & 1;
        cp16(smem_u32 + BY_W2C + (uint32_t)(n*SWC_B + p*16), (const char*)g_W2c + n*32 + p*16);
        if (tid < 32) {
            int idx2 = tid + 256;
            int n2 = idx2 >> 1, p2 = idx2 & 1;
            cp16(smem_u32 + BY_W2C + (uint32_t)(n2*SWC_B + p2*16), (const char*)g_W2c + n2*32 + p2*16);
        }
    }
    cp_commit();

    // ---- epilogue 1: softplus -> fp16 A2 ----
    #pragma unroll
    for (int mf = 0; mf < 2; mf++) {
        #pragma unroll
        for (int nf = 0; nf < 8; nf++) {
            int col = nq*64 + nf*8 + 2*t;
            float2 bb = *(float2*)&b1s[col];
            int row0 = arow + mf*16 + g;
            float2 v01 = __half22float2(*(__half2*)&acch[mf][nf][0]);
            float2 v23 = __half22float2(*(__half2*)&acch[mf][nf][1]);
            float r0 = softplus100b(v01.x, bb.x);
            float r1 = softplus100b(v01.y, bb.y);
            float r2 = softplus100b(v23.x, bb.x);
            float r3 = softplus100b(v23.y, bb.y);
            *(__half2*)(smem + BY_A2 + row0*SA2_B + col*2)     = __floats2half2_rn(r0, r1);
            *(__half2*)(smem + BY_A2 + (row0+8)*SA2_B + col*2) = __floats2half2_rn(r2, r3);
        }
    }

    cp_wait0();
    __syncthreads();

    // ================= GEMM2: 8 warps = 4m(16) x 2n(72), 16 k16-chunks, f32 acc ======
    const int mt2 = warp & 3;
    const int nh2 = warp >> 2;         // 0..1
    const int arow2 = mt2 * 16;

    const uint32_t aAddr2 = smem_u32 + BY_A2 + (uint32_t)(arow2 + lrow)*SA2_B + koffb;
    const uint32_t bRow2  = (uint32_t)(nh2*72 + lrow)*SWC_B + koffb;
    const uint32_t bRow2e = (uint32_t)(nh2*72 + 64 + (lane & 7))*SWC_B + ((lane >> 3) & 1)*16;

    float acc2[9][4];
    #pragma unroll
    for (int j = 0; j < 9; j++)
        #pragma unroll
        for (int q = 0; q < 4; q++) acc2[j][q] = 0.f;

    #pragma unroll 1
    for (int c = 0; c < 16; c++) {
        if (c < 15) {
            uint32_t dbase = smem_u32 + BY_W2C + (uint32_t)(((c+1)&1)*CH2_SZ);
            const char* src = (const char*)g_W2c + (c+1)*4608;
            int n = tid >> 1, p = tid & 1;
            cp16(dbase + (uint32_t)(n*SWC_B + p*16), src + n*32 + p*16);
            if (tid < 32) {
                int idx2 = tid + 256;
                int n2 = idx2 >> 1, p2 = idx2 & 1;
                cp16(dbase + (uint32_t)(n2*SWC_B + p2*16), src + n2*32 + p2*16);
            }
            cp_commit();
        }
        uint32_t bufb = smem_u32 + BY_W2C + (uint32_t)((c&1)*CH2_SZ);
        unsigned a0, a1, a2, a3;
        ldsm_x4(a0, a1, a2, a3, aAddr2 + c*32);
        #pragma unroll
        for (int p = 0; p < 4; p++) {
            unsigned b0, b1x, b2x, b3;
            ldsm_x4(b0, b1x, b2x, b3, bufb + bRow2 + (uint32_t)p*16*SWC_B);
            mma_f16_k16(acc2[2*p],   a0, a1, a2, a3, b0, b2x);
            mma_f16_k16(acc2[2*p+1], a0, a1, a2, a3, b1x, b3);
        }
        {
            unsigned b0, b1x;
            ldsm_x2(b0, b1x, bufb + bRow2e);
            mma_f16_k16(acc2[8], a0, a1, a2, a3, b0, b1x);
        }
        if (c < 15) cp_wait0();
        __syncthreads();
    }

    // ---- epilogue 2: bias + streaming store ----
    #pragma unroll
    for (int nf = 0; nf < 9; nf++) {
        int col = nh2*72 + nf*8 + 2*t;
        float2 bb = *(float2*)&b2s[col];
        float o0 = acc2[nf][0] + bb.x;
        float o1 = acc2[nf][1] + bb.y;
        float o2 = acc2[nf][2] + bb.x;
        float o3 = acc2[nf][3] + bb.y;
        int r0 = (pbase + arow2 + g) * NOUT;
        int r1 = r0 + 8*NOUT;
        if (col < NOUT)     { __stcs(&out[r0 + col], o0);     __stcs(&out[r1 + col], o2); }
        if (col + 1 < NOUT) { __stcs(&out[r0 + col + 1], o1); __stcs(&out[r1 + col + 1], o3); }
    }
}

extern "C" void kernel_launch(void* const* d_in, const int* in_sizes, int n_in,
                              void* d_out, int out_size) {
    const float* xyz    = (const float*)d_in[0];
    const float* planes = (const float*)d_in[1];
    const float* lines  = (const float*)d_in[2];
    const float* W1     = (const float*)d_in[3];
    const float* b1     = (const float*)d_in[4];
    const float* W2     = (const float*)d_in[5];
    const float* b2     = (const float*)d_in[6];
    float* out = (float*)d_out;

    static bool attr_set = false;
    if (!attr_set) {
        cudaFuncSetAttribute(tensosdf_main,
                             cudaFuncAttributeMaxDynamicSharedMemorySize, SMEM_BYTES);
        attr_set = true;
    }

    transpose_planes<<<3072, 256>>>(planes);
    transpose_lines<<<6, 256>>>(lines);
    const int npack = 8*256*16 + 256*8 + 16*144*16;
    pack_weights_kernel<<<(npack + 255) / 256, 256>>>(W1, W2);
    tensosdf_main<<<NPTS / TB, NTHREADS, SMEM_BYTES>>>(xyz, b1, b2, out);
}

// round 17
// speedup vs baseline: 1.0478x; 1.0478x over previous
#include <cuda_runtime.h>
#include <cuda_fp16.h>
#include <math.h>
#include <stdint.h>

#define NPTS      524288
#define GRIDSZ    512
#define NC        36
#define KIN       129
#define HID       256
#define NOUT      129
#define TB        64
#define NTHREADS  256

// ---- smem byte layout (per CTA, 3 CTAs/SM, 75776 B) ----
// phase1: W1 chunk dbl buf [0,40960) ; W1 tail [40960,45056) ; A1 [45056,62464)
// phase2: A2 [0,33792) ; W2 k64 chunk dbl buf [33792,75264)
// bias:   hb1 (fp16 100*b1) [75264,75776)
#define BY_WC   0
#define CH1_SZ  20480      // 256 rows x 80 B
#define BY_WT   40960      // 256 rows x 16 B
#define BY_A1   45056
#define BY_A2   0
#define BY_W2C  33792
#define CH2_SZ  20736      // 144 rows x 144 B
#define BY_HB1  75264
#define SMEM_BYTES 75776

#define SWC_B  80         // W1 chunk row stride; conflict-free
#define SW2C_B 144        // W2 chunk row stride; 36r%32=4r -> conflict-free
#define SA1_B  272
#define SA2_B  528
#define N2PAD  144

__device__ __align__(16) __half g_planesTh[3*GRIDSZ*GRIDSZ*NC]; // [i][y][x][c]
__device__ __align__(16) __half g_linesTh[3*GRIDSZ*NC];
__device__ __align__(16) __half g_W1c[4*256*32];  // [chunk][n][k'] k=0..127
__device__ __align__(16) __half g_W1t[256*8];     // [n][k'] k=128..135 (zero-padded)
__device__ __align__(16) __half g_W2c[4*144*64];  // [chunk][n][k'] n zero-padded >=129

// ================= prep kernels =================
__global__ void __launch_bounds__(256) transpose_planes(const float* __restrict__ planes) {
    __shared__ float tile[8][32*37];
    int wid = threadIdx.x >> 5, lane = threadIdx.x & 31;
    int cell0 = (blockIdx.x * 8 + wid) * 32;
    int i = cell0 / (GRIDSZ*GRIDSZ);
    int rem = cell0 - i*GRIDSZ*GRIDSZ;
    int y = rem >> 9, x0 = rem & (GRIDSZ-1);
    const float* src = planes + (long)i*NC*GRIDSZ*GRIDSZ + (long)y*GRIDSZ + x0 + lane;
    float* t = tile[wid];
    #pragma unroll
    for (int c = 0; c < NC; c++) t[lane*37 + c] = src[(long)c*GRIDSZ*GRIDSZ];
    __syncwarp();
    __half2* dst = (__half2*)(g_planesTh + (long)cell0 * NC);
    #pragma unroll
    for (int k = 0; k < 18; k++) {
        int h2i = k*32 + lane;
        int e0 = h2i*2;
        int cc = e0 / NC, c = e0 - cc*NC;
        dst[h2i] = __floats2half2_rn(t[cc*37+c], t[cc*37+c+1]);
    }
}

__global__ void transpose_lines(const float* __restrict__ lines) {
    int t2 = blockIdx.x * blockDim.x + threadIdx.x;
    if (t2 < 3*GRIDSZ) {
        int j = t2 & (GRIDSZ-1), i = t2 >> 9;
        __half* dst = g_linesTh + t2*NC;
        const float* src = lines + (long)i*NC*GRIDSZ + j;
        #pragma unroll
        for (int c = 0; c < NC; c++) dst[c] = __float2half_rn(src[(long)c*GRIDSZ]);
    }
}

__global__ void pack_weights_kernel(const float* __restrict__ W1, const float* __restrict__ W2) {
    int idx = blockIdx.x * blockDim.x + threadIdx.x;
    const int T1 = 4*256*32;            // 32768
    const int T2 = 256*8;               // 2048
    const int T3 = 4*144*64;            // 36864
    if (idx < T1) {
        int c = idx >> 13, rem = idx & 8191;
        int n = rem >> 5, kp = rem & 31;
        int k = c*32 + kp;              // 0..127 < KIN
        g_W1c[idx] = __float2half_rn(W1[k*HID + n]);
    } else if (idx < T1 + T2) {
        int j = idx - T1;
        int n = j >> 3, kp = j & 7;
        int k = 128 + kp;
        g_W1t[j] = (k < KIN) ? __float2half_rn(W1[k*HID + n]) : __float2half_rn(0.f);
    } else if (idx < T1 + T2 + T3) {
        int j = idx - T1 - T2;
        int c = j / 9216, r = j - c*9216;
        int n = r >> 6, kp = r & 63;
        int k = c*64 + kp;
        float v = (n < NOUT) ? W2[k*NOUT + n] : 0.f;
        g_W2c[j] = __float2half_rn(v);
    }
}

// ================= mma / ldmatrix helpers =================
__device__ __forceinline__ void mma_f16_k16(float c[4], unsigned a0, unsigned a1,
                                            unsigned a2, unsigned a3,
                                            unsigned b0, unsigned b1) {
    asm volatile(
        "mma.sync.aligned.m16n8k16.row.col.f32.f16.f16.f32 "
        "{%0,%1,%2,%3},{%4,%5,%6,%7},{%8,%9},{%0,%1,%2,%3};"
        : "+f"(c[0]), "+f"(c[1]), "+f"(c[2]), "+f"(c[3])
        : "r"(a0), "r"(a1), "r"(a2), "r"(a3), "r"(b0), "r"(b1));
}
__device__ __forceinline__ void mma_h_k16(unsigned& d0, unsigned& d1,
                                          unsigned a0, unsigned a1, unsigned a2, unsigned a3,
                                          unsigned b0, unsigned b1) {
    asm volatile(
        "mma.sync.aligned.m16n8k16.row.col.f16.f16.f16.f16 "
        "{%0,%1},{%2,%3,%4,%5},{%6,%7},{%0,%1};"
        : "+r"(d0), "+r"(d1)
        : "r"(a0), "r"(a1), "r"(a2), "r"(a3), "r"(b0), "r"(b1));
}
__device__ __forceinline__ void mma_h_k8(unsigned& d0, unsigned& d1,
                                         unsigned a0, unsigned a1, unsigned b0) {
    asm volatile(
        "mma.sync.aligned.m16n8k8.row.col.f16.f16.f16.f16 "
        "{%0,%1},{%2,%3},{%4},{%0,%1};"
        : "+r"(d0), "+r"(d1) : "r"(a0), "r"(a1), "r"(b0));
}
__device__ __forceinline__ void ldsm_x4(unsigned& r0, unsigned& r1, unsigned& r2, unsigned& r3,
                                        uint32_t a) {
    asm volatile("ldmatrix.sync.aligned.m8n8.x4.shared.b16 {%0,%1,%2,%3}, [%4];"
                 : "=r"(r0), "=r"(r1), "=r"(r2), "=r"(r3) : "r"(a));
}
__device__ __forceinline__ void ldsm_x2(unsigned& r0, unsigned& r1, uint32_t a) {
    asm volatile("ldmatrix.sync.aligned.m8n8.x2.shared.b16 {%0,%1}, [%2];"
                 : "=r"(r0), "=r"(r1) : "r"(a));
}

__device__ __forceinline__ float softplus100b(float z, float b100) {
    float y = fmaf(z, 100.f, b100);
    float e = __expf(-fabsf(y));
    return 0.01f * (fmaxf(y, 0.f) + __logf(1.f + e));
}
__device__ __forceinline__ void cp16(uint32_t dst, const void* src) {
    asm volatile("cp.async.cg.shared.global [%0], [%1], 16;" :: "r"(dst), "l"(src));
}
__device__ __forceinline__ void cp_commit() { asm volatile("cp.async.commit_group;"); }
__device__ __forceinline__ void cp_wait0()  { asm volatile("cp.async.wait_group 0;" ::: "memory"); }

// ================= main fused kernel (3 CTAs/SM) =================
__global__ void __launch_bounds__(NTHREADS, 3)
tensosdf_main(const float* __restrict__ xyz,
              const float* __restrict__ b1, const float* __restrict__ b2,
              float* __restrict__ out) {
    extern __shared__ char smem[];
    const uint32_t smem_u32 = (uint32_t)__cvta_generic_to_shared(smem);
    __half2* hb1 = (__half2*)(smem + BY_HB1);  // fp16 100*b1

    const int tid  = threadIdx.x;
    const int lane = tid & 31;
    const int warp = tid >> 5;            // 0..7
    const int pbase = blockIdx.x * TB;
    const int g = lane >> 2;
    const int t = lane & 3;

    // ---- bias table ----
    if (tid < 128)
        hb1[tid] = __floats2half2_rn(100.f*b1[2*tid], 100.f*b1[2*tid+1]);

    // ---- prestage W1 chunk 0 + tail (overlaps gather) ----
    for (int idx = tid; idx < 1024; idx += NTHREADS) {
        int n = idx >> 2, p = idx & 3;
        cp16(smem_u32 + BY_WC + (uint32_t)(n*SWC_B + p*16),
             (const char*)g_W1c + n*64 + p*16);
    }
    for (int idx = tid; idx < 256; idx += NTHREADS)
        cp16(smem_u32 + BY_WT + (uint32_t)idx*16u, (const char*)g_W1t + idx*16);
    cp_commit();

    // ---- gather: warp handles 8 points, fp16 tables, writes fp16 A1 ----
    {
        const unsigned FULL = 0xffffffffu;
        float vload = 0.f;
        int base3 = (pbase + warp*8)*3;
        if (lane < 24) vload = xyz[base3 + lane];

        const int i_of = (lane < 9) ? 0 : ((lane < 18) ? 1 : 2);
        const int cj = (lane - i_of*9) * 4;
        const bool act = lane < 27;
        const int fcol = i_of*NC + cj;
        const int pcol = 108 + lane;

        #pragma unroll
        for (int pi = 0; pi < 8; pi++) {
            float x0 = __shfl_sync(FULL, vload, pi*3+0);
            float x1 = __shfl_sync(FULL, vload, pi*3+1);
            float x2 = __shfl_sync(FULL, vload, pi*3+2);
            float xn0 = 2.f*x0 - 1.f, xn1 = 2.f*x1 - 1.f, xn2 = 2.f*x2 - 1.f;
            int row = warp*8 + pi;
            char* rbase = smem + BY_A1 + row*SA1_B;

            if (act) {
                float gx = (i_of == 2) ? xn1 : xn0;
                float gy = (i_of == 0) ? xn1 : xn2;
                float gl = (i_of == 0) ? xn2 : ((i_of == 1) ? xn1 : xn0);
                float px = (gx + 1.f) * 0.5f * 511.f;
                float py = (gy + 1.f) * 0.5f * 511.f;
                float pl = (gl + 1.f) * 0.5f * 511.f;
                int ix = min(max((int)floorf(px), 0), 510);
                int iy = min(max((int)floorf(py), 0), 510);
                int il = min(max((int)floorf(pl), 0), 510);
                float wx = px - ix, wy = py - iy, wl = pl - il;
                const __half* pb = g_planesTh + ((long)((i_of*GRIDSZ + iy)*GRIDSZ) + ix)*NC + cj;
                const __half* lb = g_linesTh + (i_of*GRIDSZ + il)*NC + cj;
                uint2 u00 = *(const uint2*)pb;
                uint2 u01 = *(const uint2*)(pb + NC);
                uint2 u10 = *(const uint2*)(pb + GRIDSZ*NC);
                uint2 u11 = *(const uint2*)(pb + GRIDSZ*NC + NC);
                uint2 ul0 = *(const uint2*)lb;
                uint2 ul1 = *(const uint2*)(lb + NC);
                float2 f00a = __half22float2(*(__half2*)&u00.x), f00b = __half22float2(*(__half2*)&u00.y);
                float2 f01a = __half22float2(*(__half2*)&u01.x), f01b = __half22float2(*(__half2*)&u01.y);
                float2 f10a = __half22float2(*(__half2*)&u10.x), f10b = __half22float2(*(__half2*)&u10.y);
                float2 f11a = __half22float2(*(__half2*)&u11.x), f11b = __half22float2(*(__half2*)&u11.y);
                float2 l0a  = __half22float2(*(__half2*)&ul0.x), l0b  = __half22float2(*(__half2*)&ul0.y);
                float2 l1a  = __half22float2(*(__half2*)&ul1.x), l1b  = __half22float2(*(__half2*)&ul1.y);
                float rx, ry, rz, rw;
                float fx0, fx1;
                fx0 = f00a.x + wx*(f01a.x - f00a.x); fx1 = f10a.x + wx*(f11a.x - f10a.x);
                rx = (fx0 + wy*(fx1 - fx0)) * (l0a.x + wl*(l1a.x - l0a.x));
                fx0 = f00a.y + wx*(f01a.y - f00a.y); fx1 = f10a.y + wx*(f11a.y - f10a.y);
                ry = (fx0 + wy*(fx1 - fx0)) * (l0a.y + wl*(l1a.y - l0a.y));
                fx0 = f00b.x + wx*(f01b.x - f00b.x); fx1 = f10b.x + wx*(f11b.x - f10b.x);
                rz = (fx0 + wy*(fx1 - fx0)) * (l0b.x + wl*(l1b.x - l0b.x));
                fx0 = f00b.y + wx*(f01b.y - f00b.y); fx1 = f10b.y + wx*(f11b.y - f10b.y);
                rw = (fx0 + wy*(fx1 - fx0)) * (l0b.y + wl*(l1b.y - l0b.y));
                *(__half2*)(rbase + fcol*2)     = __floats2half2_rn(rx, ry);
                *(__half2*)(rbase + fcol*2 + 4) = __floats2half2_rn(rz, rw);
            }

            float pv;
            if (lane < 3) pv = (lane == 0) ? xn0 : ((lane == 1) ? xn1 : xn2);
            else if (lane < 21) {
                int j = lane - 3, f = j / 6, rr = j - 6*f, d = rr % 3;
                float xv = ((d == 0) ? xn0 : ((d == 1) ? xn1 : xn2)) * (float)(1 << f);
                pv = (rr < 3) ? __sinf(xv) : __cosf(xv);
            } else pv = 0.f;
            if (pcol < 136)
                *(__half*)(rbase + pcol*2) = __float2half_rn(pv);
        }
    }

    cp_wait0();
    __syncthreads();

    // ================= GEMM1: 8 warps = 2m(32) x 4n(64), 4 k32-chunks, fp16 acc ======
    const int mt = warp & 1;
    const int nq = warp >> 1;          // 0..3
    const int arow = mt * 32;

    const int lrow  = (lane & 7) + ((lane >> 3) & 1) * 8;
    const int koffb = (lane >> 4) * 16;

    const uint32_t aAddr1 = smem_u32 + BY_A1 + (uint32_t)(arow + lrow)*SA1_B + koffb;
    const uint32_t bRow1  = (uint32_t)(nq*64 + lrow)*SWC_B + koffb;

    unsigned acch[2][8][2];
    #pragma unroll
    for (int i = 0; i < 2; i++)
        #pragma unroll
        for (int j = 0; j < 8; j++) { acch[i][j][0] = 0u; acch[i][j][1] = 0u; }

    // --- k8 tail first (k=128..135) from WT buffer ---
    {
        unsigned a0, a1, a4, a5;
        ldsm_x2(a0, a1, smem_u32 + BY_A1 + (uint32_t)(arow + lrow)*SA1_B + 256);
        ldsm_x2(a4, a5, smem_u32 + BY_A1 + (uint32_t)(arow + 16 + lrow)*SA1_B + 256);
        #pragma unroll
        for (int p = 0; p < 4; p++) {
            unsigned b0, b1x;
            ldsm_x2(b0, b1x, smem_u32 + BY_WT + (uint32_t)(nq*64 + p*16 + lrow)*16);
            mma_h_k8(acch[0][2*p][0],   acch[0][2*p][1],   a0, a1, b0);
            mma_h_k8(acch[0][2*p+1][0], acch[0][2*p+1][1], a0, a1, b1x);
            mma_h_k8(acch[1][2*p][0],   acch[1][2*p][1],   a4, a5, b0);
            mma_h_k8(acch[1][2*p+1][0], acch[1][2*p+1][1], a4, a5, b1x);
        }
    }

    // --- 4 chunks of 32 k ---
    #pragma unroll 1
    for (int c = 0; c < 4; c++) {
        if (c < 3) {
            uint32_t dbase = smem_u32 + BY_WC + (uint32_t)(((c+1)&1)*CH1_SZ);
            const char* src = (const char*)g_W1c + (c+1)*16384;
            for (int idx = tid; idx < 1024; idx += NTHREADS) {
                int n = idx >> 2, p = idx & 3;
                cp16(dbase + (uint32_t)(n*SWC_B + p*16), src + n*64 + p*16);
            }
            cp_commit();
        }
        uint32_t bufb = smem_u32 + BY_WC + (uint32_t)((c&1)*CH1_SZ);
        #pragma unroll
        for (int ks = 0; ks < 2; ks++) {
            unsigned a0, a1, a2, a3, a4, a5, a6, a7;
            ldsm_x4(a0, a1, a2, a3, aAddr1 + c*64 + ks*32);
            ldsm_x4(a4, a5, a6, a7, aAddr1 + 16*SA1_B + c*64 + ks*32);
            #pragma unroll
            for (int p = 0; p < 4; p++) {
                unsigned b0, b1x, b2x, b3;
                ldsm_x4(b0, b1x, b2x, b3, bufb + bRow1 + (uint32_t)p*16*SWC_B + ks*32);
                mma_h_k16(acch[0][2*p][0],   acch[0][2*p][1],   a0, a1, a2, a3, b0, b2x);
                mma_h_k16(acch[0][2*p+1][0], acch[0][2*p+1][1], a0, a1, a2, a3, b1x, b3);
                mma_h_k16(acch[1][2*p][0],   acch[1][2*p][1],   a4, a5, a6, a7, b0, b2x);
                mma_h_k16(acch[1][2*p+1][0], acch[1][2*p+1][1], a4, a5, a6, a7, b1x, b3);
            }
        }
        if (c < 3) cp_wait0();
        __syncthreads();
    }

    // ---- stage W2 chunk 0 (A1 now dead; region overlaps old A1) ----
    for (int idx = tid; idx < 1152; idx += NTHREADS) {
        int n = idx >> 3, p = idx & 7;
        cp16(smem_u32 + BY_W2C + (uint32_t)(n*SW2C_B + p*16),
             (const char*)g_W2c + n*128 + p*16);
    }
    cp_commit();

    // ---- epilogue 1: softplus -> fp16 A2 ----
    #pragma unroll
    for (int mf = 0; mf < 2; mf++) {
        #pragma unroll
        for (int nf = 0; nf < 8; nf++) {
            int col = nq*64 + nf*8 + 2*t;
            float2 bb = __half22float2(hb1[col >> 1]);
            int row0 = arow + mf*16 + g;
            float2 v01 = __half22float2(*(__half2*)&acch[mf][nf][0]);
            float2 v23 = __half22float2(*(__half2*)&acch[mf][nf][1]);
            float r0 = softplus100b(v01.x, bb.x);
            float r1 = softplus100b(v01.y, bb.y);
            float r2 = softplus100b(v23.x, bb.x);
            float r3 = softplus100b(v23.y, bb.y);
            *(__half2*)(smem + BY_A2 + row0*SA2_B + col*2)     = __floats2half2_rn(r0, r1);
            *(__half2*)(smem + BY_A2 + (row0+8)*SA2_B + col*2) = __floats2half2_rn(r2, r3);
        }
    }

    cp_wait0();
    __syncthreads();

    // ================= GEMM2: 8 warps = 4m(16) x 2n(72), 4 k64-chunks, f32 acc ======
    const int mt2 = warp & 3;
    const int nh2 = warp >> 2;         // 0..1
    const int arow2 = mt2 * 16;

    const uint32_t aAddr2 = smem_u32 + BY_A2 + (uint32_t)(arow2 + lrow)*SA2_B + koffb;
    const uint32_t bRow2  = (uint32_t)(nh2*72 + lrow)*SW2C_B + koffb;
    const uint32_t bRow2e = (uint32_t)(nh2*72 + 64 + (lane & 7))*SW2C_B + ((lane >> 3) & 1)*16;

    float acc2[9][4];
    #pragma unroll
    for (int j = 0; j < 9; j++)
        #pragma unroll
        for (int q = 0; q < 4; q++) acc2[j][q] = 0.f;

    #pragma unroll 1
    for (int c = 0; c < 4; c++) {
        if (c < 3) {
            uint32_t dbase = smem_u32 + BY_W2C + (uint32_t)(((c+1)&1)*CH2_SZ);
            const char* src = (const char*)g_W2c + (c+1)*18432;
            for (int idx = tid; idx < 1152; idx += NTHREADS) {
                int n = idx >> 3, p = idx & 7;
                cp16(dbase + (uint32_t)(n*SW2C_B + p*16), src + n*128 + p*16);
            }
            cp_commit();
        }
        uint32_t bufb = smem_u32 + BY_W2C + (uint32_t)((c&1)*CH2_SZ);
        #pragma unroll
        for (int ks = 0; ks < 4; ks++) {
            unsigned a0, a1, a2, a3;
            ldsm_x4(a0, a1, a2, a3, aAddr2 + c*128 + ks*32);
            #pragma unroll
            for (int p = 0; p < 4; p++) {
                unsigned b0, b1x, b2x, b3;
                ldsm_x4(b0, b1x, b2x, b3, bufb + bRow2 + (uint32_t)p*16*SW2C_B + ks*32);
                mma_f16_k16(acc2[2*p],   a0, a1, a2, a3, b0, b2x);
                mma_f16_k16(acc2[2*p+1], a0, a1, a2, a3, b1x, b3);
            }
            {
                unsigned b0, b1x;
                ldsm_x2(b0, b1x, bufb + bRow2e + ks*32);
                mma_f16_k16(acc2[8], a0, a1, a2, a3, b0, b1x);
            }
        }
        if (c < 3) cp_wait0();
        __syncthreads();
    }

    // ---- epilogue 2: bias (via __ldg) + streaming store ----
    #pragma unroll
    for (int nf = 0; nf < 9; nf++) {
        int col = nh2*72 + nf*8 + 2*t;
        int r0 = (pbase + arow2 + g) * NOUT;
        int r1 = r0 + 8*NOUT;
        if (col < NOUT) {
            float bb = __ldg(&b2[col]);
            __stcs(&out[r0 + col], acc2[nf][0] + bb);
            __stcs(&out[r1 + col], acc2[nf][2] + bb);
        }
        if (col + 1 < NOUT) {
            float bb = __ldg(&b2[col+1]);
            __stcs(&out[r0 + col + 1], acc2[nf][1] + bb);
            __stcs(&out[r1 + col + 1], acc2[nf][3] + bb);
        }
    }
}

extern "C" void kernel_launch(void* const* d_in, const int* in_sizes, int n_in,
                              void* d_out, int out_size) {
    const float* xyz    = (const float*)d_in[0];
    const float* planes = (const float*)d_in[1];
    const float* lines  = (const float*)d_in[2];
    const float* W1     = (const float*)d_in[3];
    const float* b1     = (const float*)d_in[4];
    const float* W2     = (const float*)d_in[5];
    const float* b2     = (const float*)d_in[6];
    float* out = (float*)d_out;

    static bool attr_set = false;
    if (!attr_set) {
        cudaFuncSetAttribute(tensosdf_main,
                             cudaFuncAttributeMaxDynamicSharedMemorySize, SMEM_BYTES);
        attr_set = true;
    }

    transpose_planes<<<3072, 256>>>(planes);
    transpose_lines<<<6, 256>>>(lines);
    const int npack = 4*256*32 + 256*8 + 4*144*64;
    pack_weights_kernel<<<(npack + 255) / 256, 256>>>(W1, W2);
    tensosdf_main<<<NPTS / TB, NTHREADS, SMEM_BYTES>>>(xyz, b1, b2, out);
}